// round 15
// baseline (speedup 1.0000x reference)
#include <cuda_runtime.h>
#include <math_constants.h>
#include <cstdint>

#define BB 8
#define CC 256
#define HH 128
#define WW 128
#define HW (HH*WW)
#define TOPK 10
#define THRESH 0.5f
#define MARGIN 0.5f
#define EPSV 1e-8f
#define NMAPS 16
#define NSLICE 32                  // stream slices per map (4 rows each)
#define NREG 8                     // regions per map (16 rows each)
#define JPIX (16*WW)
#define PADW 130
#define STG_ROWS 18
#define NT 256
#define CAP 512

// scratch (no allocations); all counters self-reset -> graph-replay-safe
__device__ float    g_intensity[NMAPS][HW];
__device__ float    g_part_val[NMAPS][NREG][TOPK];
__device__ int      g_part_idx[NMAPS][NREG][TOPK];
__device__ float    g_losses[BB];
__device__ unsigned g_reg_cnt[NMAPS][NREG];
__device__ unsigned g_samp_cnt[BB];
__device__ unsigned g_done_cnt;

__device__ __forceinline__ unsigned redux_max_u32(unsigned v) {
    unsigned r;
    asm volatile("redux.sync.max.u32 %0, %1, 0xffffffff;" : "=r"(r) : "r"(v));
    return r;
}
__device__ __forceinline__ unsigned redux_min_u32(unsigned v) {
    unsigned r;
    asm volatile("redux.sync.min.u32 %0, %1, 0xffffffff;" : "=r"(r) : "r"(v));
    return r;
}

__global__ void __launch_bounds__(NT, 2) fused_kernel(
    const float* __restrict__ det, const float* __restrict__ loc,
    float* __restrict__ out)
{
    __shared__ float sbuf[5120];                   // 20KB phase-union
    float4* s_part = (float4*)sbuf;                // stream: 128 float4
    float*  rawp   = sbuf;                         // region: 18*130 = 2340
    float*  s_cval = sbuf + 2560;                  // region: CAP
    int*    s_cidx = (int*)(sbuf + 2560 + CAP);    // region: CAP
    float (*df)[CC] = (float(*)[CC])sbuf;          // loss alias
    float (*lf)[CC] = (float(*)[CC])(sbuf + 2560);

    __shared__ float s_mv[2][NREG * TOPK];
    __shared__ int   s_mi[2][NREG * TOPK];
    __shared__ float s_dkv[TOPK], s_lkv[TOPK];
    __shared__ int   s_dki[TOPK], s_lki[TOPK];
    __shared__ float s_na[TOPK], s_nb[TOPK], s_ws[8];
    __shared__ int   s_cn, s_claims[2], s_nclaim, s_doloss;

    const int tid  = threadIdx.x;
    const int lane = tid & 31;
    const int w    = tid >> 5;
    const int bid  = blockIdx.x;                   // 0..511
    const int m    = bid >> 5;                     // map 0..15
    const int sl   = bid & 31;                     // slice (rows 4sl..4sl+3)
    const int b    = m & 7;

    // ============ Phase S: intensity stream (R11 verbatim: ~4.2TB/s floor) ==
    {
        const int half = tid >> 7;
        const int gl   = tid & 127;
        const int g    = sl * 128 + gl;
        const float* src = (m < 8) ? det : loc;
        const float4* base = ((const float4*)(src + (size_t)b * CC * HW))
                             + g + (size_t)half * 128 * (HW / 4);

        float a0 = 0.f, a1 = 0.f, a2 = 0.f, a3 = 0.f;
        #pragma unroll 1
        for (int c0 = 0; c0 < 128; c0 += 8) {
            float4 v[8];
            #pragma unroll
            for (int i = 0; i < 8; i++)
                v[i] = __ldcs(base + (size_t)(c0 + i) * (HW / 4));
            #pragma unroll
            for (int i = 0; i < 8; i++) {
                a0 = fmaf(v[i].x, v[i].x, a0);
                a1 = fmaf(v[i].y, v[i].y, a1);
                a2 = fmaf(v[i].z, v[i].z, a2);
                a3 = fmaf(v[i].w, v[i].w, a3);
            }
        }
        if (half) s_part[gl] = make_float4(a0, a1, a2, a3);
        __syncthreads();
        if (!half) {
            float4 p = s_part[gl];
            float4 o;
            o.x = sqrtf(a0 + p.x);
            o.y = sqrtf(a1 + p.y);
            o.z = sqrtf(a2 + p.z);
            o.w = sqrtf(a3 + p.w);
            ((float4*)g_intensity[m])[g] = o;
        }
        __syncthreads();
    }

    // ============ Claim regions completed by this slice (R7 logic) ==========
    if (tid == 0) {
        __threadfence();
        int nc = 0;
        s_doloss = 0;
        #pragma unroll
        for (int j = 0; j < NREG; j++) {
            int lo = max(0, 16 * j - 1);
            int hi = min(HH - 1, 16 * j + 16);
            if (lo <= 4 * sl + 3 && hi >= 4 * sl) {
                unsigned target = (unsigned)(hi / 4 - lo / 4 + 1);
                unsigned old = atomicAdd(&g_reg_cnt[m][j], 1u);
                if (old == target - 1u) {
                    g_reg_cnt[m][j] = 0u;          // reset for replay
                    s_claims[nc++] = j;
                }
            }
        }
        s_nclaim = nc;
    }
    __syncthreads();
    if (s_nclaim == 0) return;

    // ============ Phase R: claimed regions (R13 compact + redux top-10) =====
    __threadfence();
    for (int r = 0; r < s_nclaim; r++) {
        const int j = s_claims[r];

        for (int i = tid; i < STG_ROWS * PADW; i += NT) rawp[i] = -CUDART_INF_F;
        __syncthreads();
        {
            const float* gi = g_intensity[m];
            for (int i = tid; i < STG_ROWS * WW; i += NT) {
                int rr = i >> 7, x = i & 127;
                int grow = j * 16 - 1 + rr;
                if (grow >= 0 && grow < HH)
                    rawp[rr * PADW + x + 1] = __ldcg(&gi[(grow << 7) + x]);
            }
            if (tid == 0) s_cn = 0;
        }
        __syncthreads();

        for (int p = tid; p < JPIX; p += NT) {
            int yl = p >> 7, x = p & 127;
            const float* c = &rawp[(yl + 1) * PADW + (x + 1)];
            float v = c[0];
            float n0 = fmaxf(fmaxf(c[-PADW - 1], c[-PADW]), c[-PADW + 1]);
            float n1 = fmaxf(c[-1], c[1]);
            float n2 = fmaxf(fmaxf(c[PADW - 1], c[PADW]), c[PADW + 1]);
            float nmax = fmaxf(fmaxf(n0, n1), n2);
            if (v > THRESH && v >= nmax) {
                int s = atomicAdd(&s_cn, 1);       // < CAP guaranteed
                s_cval[s] = v;
                s_cidx[s] = j * JPIX + p;
            }
        }
        __syncthreads();

        if (w == 0) {
            const int n = s_cn;
            for (int k = 0; k < TOPK; k++) {
                float bv = 0.f; int bi = 0x7fffffff; int bslot = -1;
                for (int p = lane; p < n; p += 32) {
                    float v = s_cval[p];
                    int   i = s_cidx[p];
                    if (v > 0.f && (v > bv || (v == bv && i < bi))) {
                        bv = v; bi = i; bslot = p;
                    }
                }
                unsigned vb = __float_as_uint(bv);
                unsigned mx = redux_max_u32(vb);
                unsigned ic = (vb == mx) ? (unsigned)bi : 0xffffffffu;
                unsigned wi = redux_min_u32(ic);
                if (mx != 0u && vb == mx && (unsigned)bi == wi)
                    s_cval[bslot] = 0.f;
                if (lane == 0) {
                    g_part_val[m][j][k] = (mx != 0u) ? __uint_as_float(mx)
                                                     : -CUDART_INF_F;
                    g_part_idx[m][j][k] = (mx != 0u) ? (int)wi : 0;
                }
                __syncwarp();
            }
        }
        __syncthreads();

        if (tid == 0) {
            __threadfence();
            unsigned old = atomicAdd(&g_samp_cnt[b], 1u);
            if (old == 15u) { g_samp_cnt[b] = 0u; s_doloss = 1; }
        }
        __syncthreads();
    }
    if (!s_doloss) return;

    // ============ Phase L: loss for sample b (R13 redux merges) =============
    __threadfence();
    if (w < 2) {
        const int mm = (w == 0) ? b : (8 + b);
        const float* pv = &g_part_val[mm][0][0];
        const int*   pi = &g_part_idx[mm][0][0];
        for (int p = lane; p < 80; p += 32) {
            s_mv[w][p] = __ldcg(&pv[p]);
            s_mi[w][p] = __ldcg(&pi[p]);
        }
        __syncwarp();
        for (int k = 0; k < TOPK; k++) {
            float bv = 0.f; int bi = 0x7fffffff; int bslot = -1;
            #pragma unroll
            for (int q = 0; q < 3; q++) {
                int p = q * 32 + lane;
                if (p < 80) {
                    float v = s_mv[w][p];
                    int   i = s_mi[w][p];
                    if (v > 0.f && (v > bv || (v == bv && i < bi))) {
                        bv = v; bi = i; bslot = p;
                    }
                }
            }
            unsigned vb = __float_as_uint(bv);
            unsigned mx = redux_max_u32(vb);
            unsigned ic = (vb == mx) ? (unsigned)bi : 0xffffffffu;
            unsigned wi = redux_min_u32(ic);
            if (mx != 0u && vb == mx && (unsigned)bi == wi)
                s_mv[w][bslot] = 0.f;
            if (lane == 0) {
                float fv = (mx != 0u) ? __uint_as_float(mx) : -CUDART_INF_F;
                int   fi = (mx != 0u) ? (int)wi : 0;
                if (w == 0) { s_dkv[k] = fv; s_dki[k] = fi; }
                else        { s_lkv[k] = fv; s_lki[k] = fi; }
            }
            __syncwarp();
        }
    }
    __syncthreads();   // region smem dead before alias overwrite

    {
        const float* dbase = det + (size_t)b * CC * HW;
        const float* lbase = loc + (size_t)b * CC * HW;
        for (int idx = tid; idx < TOPK * CC; idx += NT) {
            int k = idx >> 8, c = idx & 255;
            df[k][c] = __ldg(&dbase[(size_t)c * HW + s_dki[k]]);
            lf[k][c] = __ldg(&lbase[(size_t)c * HW + s_lki[k]]);
        }
    }
    __syncthreads();

    for (int k = w; k < TOPK; k += 8) {
        float sa = 0.f, sb = 0.f;
        #pragma unroll
        for (int c = lane; c < CC; c += 32) {
            sa = fmaf(df[k][c], df[k][c], sa);
            sb = fmaf(lf[k][c], lf[k][c], sb);
        }
        #pragma unroll
        for (int o = 16; o > 0; o >>= 1) {
            sa += __shfl_down_sync(0xffffffffu, sa, o);
            sb += __shfl_down_sync(0xffffffffu, sb, o);
        }
        if (lane == 0) {
            s_na[k] = fmaxf(sqrtf(sa), EPSV);
            s_nb[k] = fmaxf(sqrtf(sb), EPSV);
        }
    }
    __syncthreads();

    float lsum = 0.f;
    for (int p = w; p < TOPK * TOPK; p += 8) {
        int i = p / TOPK, jj = p % TOPK;
        float dot = 0.f;
        #pragma unroll
        for (int c = lane; c < CC; c += 32) dot = fmaf(df[i][c], lf[jj][c], dot);
        #pragma unroll
        for (int o = 16; o > 0; o >>= 1)
            dot += __shfl_down_sync(0xffffffffu, dot, o);
        if (lane == 0 && s_dkv[i] > -CUDART_INF_F && s_lkv[jj] > -CUDART_INF_F)
            lsum += fmaxf(dot / (s_na[i] * s_nb[jj]) - MARGIN, 0.f);
    }
    if (lane == 0) s_ws[w] = lsum;
    __syncthreads();

    if (tid == 0) {
        int nd = 0, nl = 0;
        #pragma unroll
        for (int k = 0; k < TOPK; k++) {
            nd += (s_dkv[k] > -CUDART_INF_F) ? 1 : 0;
            nl += (s_lkv[k] > -CUDART_INF_F) ? 1 : 0;
        }
        float ssum = 0.f;
        #pragma unroll
        for (int q = 0; q < 8; q++) ssum += s_ws[q];
        int np = nd * nl;
        g_losses[b] = (np > 0) ? (ssum / (float)np) : 0.f;

        __threadfence();
        unsigned old = atomicAdd(&g_done_cnt, 1u);
        if (old == (BB - 1)) {
            g_done_cnt = 0u;
            __threadfence();
            float tot = 0.f;
            #pragma unroll
            for (int q = 0; q < BB; q++) tot += __ldcg(&g_losses[q]);
            out[0] = tot / (float)BB;
        }
    }
}

extern "C" void kernel_launch(void* const* d_in, const int* in_sizes, int n_in,
                              void* d_out, int out_size)
{
    const float* loc = (const float*)d_in[0];   // loc_features [8,256,128,128]
    const float* det = (const float*)d_in[1];   // det_features [8,256,128,128]
    float* out = (float*)d_out;

    fused_kernel<<<NMAPS * NSLICE, NT>>>(det, loc, out);
}

// round 16
// speedup vs baseline: 1.2399x; 1.2399x over previous
#include <cuda_runtime.h>
#include <math_constants.h>
#include <cstdint>

#define BB 8
#define CC 256
#define HH 128
#define WW 128
#define HW (HH*WW)
#define TOPK 10
#define THRESH 0.5f
#define MARGIN 0.5f
#define EPSV 1e-8f
#define NMAPS 16
#define JCTAS 8                    // tail CTAs per map
#define JROWS 16
#define JPIX (JROWS*WW)            // 2048 pixels per region
#define PADW 130
#define STG_ROWS 18
#define T2 512                     // tail threads (16 warps)
#define CAP 512                    // exact max strict-3x3 maxima in 16x128

// scratch (no allocations allowed); counters self-reset -> replay-safe
__device__ float    g_intensity[NMAPS][HW];
__device__ float    g_part_val[NMAPS][JCTAS][TOPK];
__device__ int      g_part_idx[NMAPS][JCTAS][TOPK];
__device__ float    g_losses[BB];
__device__ unsigned g_samp_cnt[BB];
__device__ unsigned g_done_cnt;

__device__ __forceinline__ unsigned redux_max_u32(unsigned v) {
    unsigned r;
    asm volatile("redux.sync.max.u32 %0, %1, 0xffffffff;" : "=r"(r) : "r"(v));
    return r;
}
__device__ __forceinline__ unsigned redux_min_u32(unsigned v) {
    unsigned r;
    asm volatile("redux.sync.min.u32 %0, %1, 0xffffffff;" : "=r"(r) : "r"(v));
    return r;
}

// ---------------------------------------------------------------------------
// Kernel 1: intensity stream — R11 VERBATIM (74.2us champion; ~4.2TB/s =
// measured machine floor across LDG/TMA/layout variants). Do not touch.
// ---------------------------------------------------------------------------
__global__ void __launch_bounds__(256, 2) intensity_kernel(
    const float* __restrict__ det, const float* __restrict__ loc)
{
    __shared__ float4 s_part[128];

    const int bid  = blockIdx.x;
    const int m    = bid >> 5;
    const int sl   = bid & 31;
    const int b    = m & 7;
    const int tid  = threadIdx.x;
    const int half = tid >> 7;
    const int gl   = tid & 127;
    const int g    = sl * 128 + gl;

    const float* src = (m < 8) ? det : loc;
    const float4* base = ((const float4*)(src + (size_t)b * CC * HW))
                         + g + (size_t)half * 128 * (HW / 4);

    float a0 = 0.f, a1 = 0.f, a2 = 0.f, a3 = 0.f;
    #pragma unroll 1
    for (int c0 = 0; c0 < 128; c0 += 8) {
        float4 v[8];
        #pragma unroll
        for (int i = 0; i < 8; i++)
            v[i] = __ldcs(base + (size_t)(c0 + i) * (HW / 4));
        #pragma unroll
        for (int i = 0; i < 8; i++) {
            a0 = fmaf(v[i].x, v[i].x, a0);
            a1 = fmaf(v[i].y, v[i].y, a1);
            a2 = fmaf(v[i].z, v[i].z, a2);
            a3 = fmaf(v[i].w, v[i].w, a3);
        }
    }
    if (half) s_part[gl] = make_float4(a0, a1, a2, a3);
    __syncthreads();
    if (!half) {
        float4 p = s_part[gl];
        float4 o;
        o.x = sqrtf(a0 + p.x);
        o.y = sqrtf(a1 + p.y);
        o.z = sqrtf(a2 + p.z);
        o.w = sqrtf(a3 + p.w);
        ((float4*)g_intensity[m])[g] = o;
    }
}

// ---------------------------------------------------------------------------
// Kernel 2: tail v4 — 512 threads (2x parallelism on staging/detect/gather/
// dots), compact+redux top-10 (fewest serial ops). 128 CTAs.
// ---------------------------------------------------------------------------
__global__ void __launch_bounds__(T2, 2) tail_kernel(
    const float* __restrict__ det, const float* __restrict__ loc,
    float* __restrict__ out)
{
    __shared__ float sbuf[5120];                  // 20KB, phase-aliased
    float* rawp   = sbuf;                         // 18*130 = 2340
    float* s_cval = sbuf + 2560;                  // CAP
    int*   s_cidx = (int*)(sbuf + 2560 + CAP);    // CAP
    float (*df)[CC] = (float(*)[CC])sbuf;         // loss alias
    float (*lf)[CC] = (float(*)[CC])(sbuf + 2560);// loss alias

    __shared__ float s_mv[2][JCTAS * TOPK];
    __shared__ int   s_mi[2][JCTAS * TOPK];
    __shared__ float s_dkv[TOPK], s_lkv[TOPK];
    __shared__ int   s_dki[TOPK], s_lki[TOPK];
    __shared__ float s_na[TOPK], s_nb[TOPK], s_ws[16];
    __shared__ int   s_cn;
    __shared__ unsigned s_flag;

    const int tid  = threadIdx.x;
    const int lane = tid & 31;
    const int w    = tid >> 5;                    // 16 warps
    const int m    = blockIdx.x >> 3;             // map 0..15
    const int j    = blockIdx.x & 7;              // region
    const int b    = m & 7;

    // ---- stage 16 rows + halo into padded smem (-inf border) ---------------
    for (int i = tid; i < STG_ROWS * PADW; i += T2) rawp[i] = -CUDART_INF_F;
    __syncthreads();
    {
        const float* gi = g_intensity[m];
        for (int i = tid; i < STG_ROWS * WW; i += T2) {
            int r = i >> 7, x = i & 127;
            int grow = j * JROWS - 1 + r;
            if (grow >= 0 && grow < HH)
                rawp[r * PADW + x + 1] = __ldcg(&gi[(grow << 7) + x]);
        }
        if (tid == 0) s_cn = 0;
    }
    __syncthreads();

    // ---- branch-free 3x3 strict maxima -> compact candidate list -----------
    for (int p = tid; p < JPIX; p += T2) {
        int yl = p >> 7, x = p & 127;
        const float* c = &rawp[(yl + 1) * PADW + (x + 1)];
        float v = c[0];
        float n0 = fmaxf(fmaxf(c[-PADW - 1], c[-PADW]), c[-PADW + 1]);
        float n1 = fmaxf(c[-1], c[1]);
        float n2 = fmaxf(fmaxf(c[PADW - 1], c[PADW]), c[PADW + 1]);
        float nmax = fmaxf(fmaxf(n0, n1), n2);
        if (v > THRESH && v >= nmax) {
            int s = atomicAdd(&s_cn, 1);          // < CAP guaranteed
            s_cval[s] = v;
            s_cidx[s] = j * JPIX + p;             // global pixel index
        }
    }
    __syncthreads();

    // ---- warp 0: 10 redux-argmax passes (val desc, idx asc = lax.top_k) ----
    if (w == 0) {
        const int n = s_cn;
        for (int k = 0; k < TOPK; k++) {
            float bv = 0.f; int bi = 0x7fffffff; int bslot = -1;
            for (int p = lane; p < n; p += 32) {
                float v = s_cval[p];
                int   i = s_cidx[p];
                if (v > 0.f && (v > bv || (v == bv && i < bi))) {
                    bv = v; bi = i; bslot = p;
                }
            }
            unsigned vb = __float_as_uint(bv);
            unsigned mx = redux_max_u32(vb);
            unsigned ic = (vb == mx) ? (unsigned)bi : 0xffffffffu;
            unsigned wi = redux_min_u32(ic);
            if (mx != 0u && vb == mx && (unsigned)bi == wi)
                s_cval[bslot] = 0.f;
            if (lane == 0) {
                g_part_val[m][j][k] = (mx != 0u) ? __uint_as_float(mx)
                                                 : -CUDART_INF_F;
                g_part_idx[m][j][k] = (mx != 0u) ? (int)wi : 0;
            }
            __syncwarp();
        }
    }
    __syncthreads();
    if (tid == 0) {
        __threadfence();
        unsigned old = atomicAdd(&g_samp_cnt[b], 1u);
        if (old == 15u) g_samp_cnt[b] = 0u;       // reset for replay
        s_flag = (old == 15u);
    }
    __syncthreads();
    if (!s_flag) return;   // last of the sample's 16 region CTAs does the loss

    // ---- merge 80 partials per map via redux: warp0=det(b), warp1=loc(8+b) -
    __threadfence();
    if (w < 2) {
        const int mm = (w == 0) ? b : (8 + b);
        const float* pv = &g_part_val[mm][0][0];
        const int*   pi = &g_part_idx[mm][0][0];
        for (int p = lane; p < 80; p += 32) {
            s_mv[w][p] = __ldcg(&pv[p]);
            s_mi[w][p] = __ldcg(&pi[p]);
        }
        __syncwarp();
        for (int k = 0; k < TOPK; k++) {
            float bv = 0.f; int bi = 0x7fffffff; int bslot = -1;
            #pragma unroll
            for (int q = 0; q < 3; q++) {
                int p = q * 32 + lane;
                if (p < 80) {
                    float v = s_mv[w][p];
                    int   i = s_mi[w][p];
                    if (v > 0.f && (v > bv || (v == bv && i < bi))) {
                        bv = v; bi = i; bslot = p;
                    }
                }
            }
            unsigned vb = __float_as_uint(bv);
            unsigned mx = redux_max_u32(vb);
            unsigned ic = (vb == mx) ? (unsigned)bi : 0xffffffffu;
            unsigned wi = redux_min_u32(ic);
            if (mx != 0u && vb == mx && (unsigned)bi == wi)
                s_mv[w][bslot] = 0.f;
            if (lane == 0) {
                float fv = (mx != 0u) ? __uint_as_float(mx) : -CUDART_INF_F;
                int   fi = (mx != 0u) ? (int)wi : 0;
                if (w == 0) { s_dkv[k] = fv; s_dki[k] = fi; }
                else        { s_lkv[k] = fv; s_lki[k] = fi; }
            }
            __syncwarp();
        }
    }
    __syncthreads();   // candidate smem dead before alias overwrite

    // ---- gather features [10][256] x2 (10 scattered loads/thread) ----------
    {
        const float* dbase = det + (size_t)b * CC * HW;
        const float* lbase = loc + (size_t)b * CC * HW;
        for (int idx = tid; idx < TOPK * CC; idx += T2) {
            int k = idx >> 8, c = idx & 255;
            df[k][c] = __ldg(&dbase[(size_t)c * HW + s_dki[k]]);
            lf[k][c] = __ldg(&lbase[(size_t)c * HW + s_lki[k]]);
        }
    }
    __syncthreads();

    // ---- norms: warp k handles row k (10 of 16 warps active) ----------------
    if (w < TOPK) {
        float sa = 0.f, sb = 0.f;
        #pragma unroll
        for (int c = lane; c < CC; c += 32) {
            sa = fmaf(df[w][c], df[w][c], sa);
            sb = fmaf(lf[w][c], lf[w][c], sb);
        }
        #pragma unroll
        for (int o = 16; o > 0; o >>= 1) {
            sa += __shfl_down_sync(0xffffffffu, sa, o);
            sb += __shfl_down_sync(0xffffffffu, sb, o);
        }
        if (lane == 0) {
            s_na[w] = fmaxf(sqrtf(sa), EPSV);
            s_nb[w] = fmaxf(sqrtf(sb), EPSV);
        }
    }
    __syncthreads();

    // ---- 100 pair dots over 16 warps (7 rounds) ------------------------------
    float lsum = 0.f;
    for (int p = w; p < TOPK * TOPK; p += 16) {
        int i = p / TOPK, jj = p % TOPK;
        float dot = 0.f;
        #pragma unroll
        for (int c = lane; c < CC; c += 32) dot = fmaf(df[i][c], lf[jj][c], dot);
        #pragma unroll
        for (int o = 16; o > 0; o >>= 1)
            dot += __shfl_down_sync(0xffffffffu, dot, o);
        if (lane == 0 && s_dkv[i] > -CUDART_INF_F && s_lkv[jj] > -CUDART_INF_F)
            lsum += fmaxf(dot / (s_na[i] * s_nb[jj]) - MARGIN, 0.f);
    }
    if (lane == 0) s_ws[w] = lsum;
    __syncthreads();

    if (tid == 0) {
        int nd = 0, nl = 0;
        #pragma unroll
        for (int k = 0; k < TOPK; k++) {
            nd += (s_dkv[k] > -CUDART_INF_F) ? 1 : 0;
            nl += (s_lkv[k] > -CUDART_INF_F) ? 1 : 0;
        }
        float ssum = 0.f;
        #pragma unroll
        for (int q = 0; q < 16; q++) ssum += s_ws[q];
        int np = nd * nl;
        g_losses[b] = (np > 0) ? (ssum / (float)np) : 0.f;

        // last loss CTA writes the scalar (fixed-order sum, deterministic)
        __threadfence();
        unsigned old = atomicAdd(&g_done_cnt, 1u);
        if (old == (BB - 1)) {
            g_done_cnt = 0u;   // reset for replay
            __threadfence();
            float tot = 0.f;
            #pragma unroll
            for (int q = 0; q < BB; q++) tot += __ldcg(&g_losses[q]);
            out[0] = tot / (float)BB;
        }
    }
}

extern "C" void kernel_launch(void* const* d_in, const int* in_sizes, int n_in,
                              void* d_out, int out_size)
{
    const float* loc = (const float*)d_in[0];   // loc_features [8,256,128,128]
    const float* det = (const float*)d_in[1];   // det_features [8,256,128,128]
    float* out = (float*)d_out;

    intensity_kernel<<<512, 256>>>(det, loc);
    tail_kernel<<<NMAPS * JCTAS, T2>>>(det, loc, out);
}

// round 17
// speedup vs baseline: 1.2447x; 1.0038x over previous
#include <cuda_runtime.h>
#include <math_constants.h>
#include <cstdint>

#define BB 8
#define CC 256
#define HH 128
#define WW 128
#define HW (HH*WW)
#define TOPK 10
#define THRESH 0.5f
#define MARGIN 0.5f
#define EPSV 1e-8f
#define NMAPS 16
#define JCTAS 16                   // tail CTAs per map (8 rows each)
#define JROWS 8
#define JPIX (JROWS*WW)            // 1024 pixels per region
#define T2 512                     // tail threads (16 warps)
#define CAP 384                    // max strict 3x3 maxima in 8x128 is 256
#define NPART (JCTAS*TOPK)         // 160 partials per map

// scratch (no allocations allowed); counters self-reset -> replay-safe
__device__ float    g_intensity[NMAPS][HW];
__device__ float    g_part_val[NMAPS][JCTAS][TOPK];
__device__ int      g_part_idx[NMAPS][JCTAS][TOPK];
__device__ float    g_losses[BB];
__device__ unsigned g_samp_cnt[BB];
__device__ unsigned g_done_cnt;

__device__ __forceinline__ unsigned redux_max_u32(unsigned v) {
    unsigned r;
    asm volatile("redux.sync.max.u32 %0, %1, 0xffffffff;" : "=r"(r) : "r"(v));
    return r;
}
__device__ __forceinline__ unsigned redux_min_u32(unsigned v) {
    unsigned r;
    asm volatile("redux.sync.min.u32 %0, %1, 0xffffffff;" : "=r"(r) : "r"(v));
    return r;
}

// ---------------------------------------------------------------------------
// Kernel 1: intensity stream — R11 VERBATIM (~36us, ~7.2TB/s, at roofline).
// ---------------------------------------------------------------------------
__global__ void __launch_bounds__(256, 2) intensity_kernel(
    const float* __restrict__ det, const float* __restrict__ loc)
{
    __shared__ float4 s_part[128];

    const int bid  = blockIdx.x;
    const int m    = bid >> 5;
    const int sl   = bid & 31;
    const int b    = m & 7;
    const int tid  = threadIdx.x;
    const int half = tid >> 7;
    const int gl   = tid & 127;
    const int g    = sl * 128 + gl;

    const float* src = (m < 8) ? det : loc;
    const float4* base = ((const float4*)(src + (size_t)b * CC * HW))
                         + g + (size_t)half * 128 * (HW / 4);

    float a0 = 0.f, a1 = 0.f, a2 = 0.f, a3 = 0.f;
    #pragma unroll 1
    for (int c0 = 0; c0 < 128; c0 += 8) {
        float4 v[8];
        #pragma unroll
        for (int i = 0; i < 8; i++)
            v[i] = __ldcs(base + (size_t)(c0 + i) * (HW / 4));
        #pragma unroll
        for (int i = 0; i < 8; i++) {
            a0 = fmaf(v[i].x, v[i].x, a0);
            a1 = fmaf(v[i].y, v[i].y, a1);
            a2 = fmaf(v[i].z, v[i].z, a2);
            a3 = fmaf(v[i].w, v[i].w, a3);
        }
    }
    if (half) s_part[gl] = make_float4(a0, a1, a2, a3);
    __syncthreads();
    if (!half) {
        float4 p = s_part[gl];
        float4 o;
        o.x = sqrtf(a0 + p.x);
        o.y = sqrtf(a1 + p.y);
        o.z = sqrtf(a2 + p.z);
        o.w = sqrtf(a3 + p.w);
        ((float4*)g_intensity[m])[g] = o;
    }
}

// ---------------------------------------------------------------------------
// Kernel 2: tail v5 — 256 CTAs x 512 thr. No smem staging: detection reads
// L2 directly (2 px/thread x 9 independent loads = single latency exposure).
// Compact + redux top-10 per 8-row region; counter-gated loss.
// ---------------------------------------------------------------------------
__global__ void __launch_bounds__(T2, 2) tail_kernel(
    const float* __restrict__ det, const float* __restrict__ loc,
    float* __restrict__ out)
{
    __shared__ float sbuf[5120];                  // 20KB, phase-aliased
    float* s_cval = sbuf;                         // CAP
    int*   s_cidx = (int*)(sbuf + CAP);           // CAP
    float (*df)[CC] = (float(*)[CC])sbuf;         // loss alias (2560)
    float (*lf)[CC] = (float(*)[CC])(sbuf + 2560);// loss alias (2560)

    __shared__ float s_mv[2][NPART];
    __shared__ int   s_mi[2][NPART];
    __shared__ float s_dkv[TOPK], s_lkv[TOPK];
    __shared__ int   s_dki[TOPK], s_lki[TOPK];
    __shared__ float s_na[TOPK], s_nb[TOPK], s_ws[16];
    __shared__ int   s_cn;
    __shared__ unsigned s_flag;

    const int tid  = threadIdx.x;
    const int lane = tid & 31;
    const int w    = tid >> 5;                    // 16 warps
    const int m    = blockIdx.x >> 4;             // map 0..15
    const int j    = blockIdx.x & 15;             // region (rows 8j..8j+7)
    const int b    = m & 7;

    if (tid == 0) s_cn = 0;
    __syncthreads();

    // ---- detection straight from L2: 2 px/thread, 9 independent loads ------
    {
        const float* gi = g_intensity[m];
        #pragma unroll
        for (int r = 0; r < 2; r++) {
            int p  = tid + r * T2;                // 0..1023 region-local
            int gp = j * JPIX + p;                // global pixel
            int y  = gp >> 7, x = gp & 127;
            float v = __ldg(&gi[gp]);
            bool xl = (x > 0), xr = (x < WW - 1);
            bool yu = (y > 0), yd = (y < HH - 1);
            float nmax = -CUDART_INF_F;
            if (yu) {
                nmax = fmaxf(nmax, __ldg(&gi[gp - WW]));
                if (xl) nmax = fmaxf(nmax, __ldg(&gi[gp - WW - 1]));
                if (xr) nmax = fmaxf(nmax, __ldg(&gi[gp - WW + 1]));
            }
            if (xl) nmax = fmaxf(nmax, __ldg(&gi[gp - 1]));
            if (xr) nmax = fmaxf(nmax, __ldg(&gi[gp + 1]));
            if (yd) {
                nmax = fmaxf(nmax, __ldg(&gi[gp + WW]));
                if (xl) nmax = fmaxf(nmax, __ldg(&gi[gp + WW - 1]));
                if (xr) nmax = fmaxf(nmax, __ldg(&gi[gp + WW + 1]));
            }
            if (v > THRESH && v >= nmax) {
                int s = atomicAdd(&s_cn, 1);      // < CAP guaranteed (<=256)
                s_cval[s] = v;
                s_cidx[s] = gp;
            }
        }
    }
    __syncthreads();

    // ---- warp 0: 10 redux-argmax passes (val desc, idx asc = lax.top_k) ----
    if (w == 0) {
        const int n = s_cn;
        for (int k = 0; k < TOPK; k++) {
            float bv = 0.f; int bi = 0x7fffffff; int bslot = -1;
            for (int p = lane; p < n; p += 32) {
                float v = s_cval[p];
                int   i = s_cidx[p];
                if (v > 0.f && (v > bv || (v == bv && i < bi))) {
                    bv = v; bi = i; bslot = p;
                }
            }
            unsigned vb = __float_as_uint(bv);
            unsigned mx = redux_max_u32(vb);
            unsigned ic = (vb == mx) ? (unsigned)bi : 0xffffffffu;
            unsigned wi = redux_min_u32(ic);
            if (mx != 0u && vb == mx && (unsigned)bi == wi)
                s_cval[bslot] = 0.f;
            if (lane == 0) {
                g_part_val[m][j][k] = (mx != 0u) ? __uint_as_float(mx)
                                                 : -CUDART_INF_F;
                g_part_idx[m][j][k] = (mx != 0u) ? (int)wi : 0;
            }
            __syncwarp();
        }
    }
    __syncthreads();
    if (tid == 0) {
        __threadfence();
        unsigned old = atomicAdd(&g_samp_cnt[b], 1u);
        if (old == 2u * JCTAS - 1u) g_samp_cnt[b] = 0u;   // reset for replay
        s_flag = (old == 2u * JCTAS - 1u);
    }
    __syncthreads();
    if (!s_flag) return;   // last of the sample's 32 region CTAs does the loss

    // ---- merge 160 partials per map: warp0=det(b), warp1=loc(8+b) ----------
    __threadfence();
    if (w < 2) {
        const int mm = (w == 0) ? b : (8 + b);
        const float* pv = &g_part_val[mm][0][0];
        const int*   pi = &g_part_idx[mm][0][0];
        for (int p = lane; p < NPART; p += 32) {
            s_mv[w][p] = __ldcg(&pv[p]);
            s_mi[w][p] = __ldcg(&pi[p]);
        }
        __syncwarp();
        for (int k = 0; k < TOPK; k++) {
            float bv = 0.f; int bi = 0x7fffffff; int bslot = -1;
            #pragma unroll
            for (int q = 0; q < 5; q++) {
                int p = q * 32 + lane;
                if (p < NPART) {
                    float v = s_mv[w][p];
                    int   i = s_mi[w][p];
                    if (v > 0.f && (v > bv || (v == bv && i < bi))) {
                        bv = v; bi = i; bslot = p;
                    }
                }
            }
            unsigned vb = __float_as_uint(bv);
            unsigned mx = redux_max_u32(vb);
            unsigned ic = (vb == mx) ? (unsigned)bi : 0xffffffffu;
            unsigned wi = redux_min_u32(ic);
            if (mx != 0u && vb == mx && (unsigned)bi == wi)
                s_mv[w][bslot] = 0.f;
            if (lane == 0) {
                float fv = (mx != 0u) ? __uint_as_float(mx) : -CUDART_INF_F;
                int   fi = (mx != 0u) ? (int)wi : 0;
                if (w == 0) { s_dkv[k] = fv; s_dki[k] = fi; }
                else        { s_lkv[k] = fv; s_lki[k] = fi; }
            }
            __syncwarp();
        }
    }
    __syncthreads();   // candidate smem dead before alias overwrite

    // ---- gather features [10][256] x2 (5 iters x 2 loads/thread) -----------
    {
        const float* dbase = det + (size_t)b * CC * HW;
        const float* lbase = loc + (size_t)b * CC * HW;
        for (int idx = tid; idx < TOPK * CC; idx += T2) {
            int k = idx >> 8, c = idx & 255;
            df[k][c] = __ldg(&dbase[(size_t)c * HW + s_dki[k]]);
            lf[k][c] = __ldg(&lbase[(size_t)c * HW + s_lki[k]]);
        }
    }
    __syncthreads();

    // ---- norms: warp k handles row k ----------------------------------------
    if (w < TOPK) {
        float sa = 0.f, sb = 0.f;
        #pragma unroll
        for (int c = lane; c < CC; c += 32) {
            sa = fmaf(df[w][c], df[w][c], sa);
            sb = fmaf(lf[w][c], lf[w][c], sb);
        }
        #pragma unroll
        for (int o = 16; o > 0; o >>= 1) {
            sa += __shfl_down_sync(0xffffffffu, sa, o);
            sb += __shfl_down_sync(0xffffffffu, sb, o);
        }
        if (lane == 0) {
            s_na[w] = fmaxf(sqrtf(sa), EPSV);
            s_nb[w] = fmaxf(sqrtf(sb), EPSV);
        }
    }
    __syncthreads();

    // ---- 100 pair dots over 16 warps (7 rounds) ------------------------------
    float lsum = 0.f;
    for (int p = w; p < TOPK * TOPK; p += 16) {
        int i = p / TOPK, jj = p % TOPK;
        float dot = 0.f;
        #pragma unroll
        for (int c = lane; c < CC; c += 32) dot = fmaf(df[i][c], lf[jj][c], dot);
        #pragma unroll
        for (int o = 16; o > 0; o >>= 1)
            dot += __shfl_down_sync(0xffffffffu, dot, o);
        if (lane == 0 && s_dkv[i] > -CUDART_INF_F && s_lkv[jj] > -CUDART_INF_F)
            lsum += fmaxf(dot / (s_na[i] * s_nb[jj]) - MARGIN, 0.f);
    }
    if (lane == 0) s_ws[w] = lsum;
    __syncthreads();

    if (tid == 0) {
        int nd = 0, nl = 0;
        #pragma unroll
        for (int k = 0; k < TOPK; k++) {
            nd += (s_dkv[k] > -CUDART_INF_F) ? 1 : 0;
            nl += (s_lkv[k] > -CUDART_INF_F) ? 1 : 0;
        }
        float ssum = 0.f;
        #pragma unroll
        for (int q = 0; q < 16; q++) ssum += s_ws[q];
        int np = nd * nl;
        g_losses[b] = (np > 0) ? (ssum / (float)np) : 0.f;

        // last loss CTA writes the scalar (fixed-order sum, deterministic)
        __threadfence();
        unsigned old = atomicAdd(&g_done_cnt, 1u);
        if (old == (BB - 1)) {
            g_done_cnt = 0u;   // reset for replay
            __threadfence();
            float tot = 0.f;
            #pragma unroll
            for (int q = 0; q < BB; q++) tot += __ldcg(&g_losses[q]);
            out[0] = tot / (float)BB;
        }
    }
}

extern "C" void kernel_launch(void* const* d_in, const int* in_sizes, int n_in,
                              void* d_out, int out_size)
{
    const float* loc = (const float*)d_in[0];   // loc_features [8,256,128,128]
    const float* det = (const float*)d_in[1];   // det_features [8,256,128,128]
    float* out = (float*)d_out;

    intensity_kernel<<<512, 256>>>(det, loc);
    tail_kernel<<<NMAPS * JCTAS, T2>>>(det, loc, out);
}